// round 14
// baseline (speedup 1.0000x reference)
#include <cuda_runtime.h>
#include <math.h>

// E=8 A=128 TGT=3 HID=16 OUT=128 B=64 W=128 F=132
struct Params {
  const float *Local, *Remote;
  const float *gWih0,*gWhh0,*gbih0,*gbhh0,*gWih1,*gWhh1,*gbih1,*gbhh1;
  const float *aew1,*aeb1,*aew2,*aeb2,*aeg,*aebt;
  const float *mdw1,*mdb1,*mdw2,*mdb2,*mdg,*mdbt;
  const float *mWih0,*mWhh0,*mbih0,*mbhh0,*mWih1,*mWhh1,*mbih1,*mbhh1;
  float* out;
};

__device__ __align__(16) float g_G[128*128*8];   // gate GRU hidden (pre-softmax) [seq][t][8]
__device__ __align__(16) float g_P[16384*128];   // expert-1 GEMM result
__device__ __align__(16) float g_H[16384*16];    // mixed hidden (pre-BN)
__device__             float g_stats[64];        // [call*32 + (sum16|sumsq16)]
__device__ __align__(16) float g_XW0[8192*48];   // mixer layer0 input projection (incl. bih0)
__device__ __align__(16) float g_HF[64*16];      // mixer final hidden
__device__ __align__(16) float g_C[64*128];      // decoder: om (x) a
__device__ __align__(16) float g_OMd[64*8];      // decoder gates

#define DEVFN __device__ __forceinline__
typedef unsigned long long u64;

DEVFN u64 pk2(float lo,float hi){u64 r;asm("mov.b64 %0,{%1,%2};":"=l"(r):"f"(lo),"f"(hi));return r;}
DEVFN float hadd2(u64 v){float lo,hi;asm("mov.b64 {%0,%1},%2;":"=f"(lo),"=f"(hi):"l"(v));return lo+hi;}
DEVFN void up2(u64 v,float&lo,float&hi){asm("mov.b64 {%0,%1},%2;":"=f"(lo),"=f"(hi):"l"(v));}
DEVFN u64 fma2(u64 a,u64 b,u64 c){u64 d;asm("fma.rn.f32x2 %0,%1,%2,%3;":"=l"(d):"l"(a),"l"(b),"l"(c));return d;}
DEVFN u64 add2(u64 a,u64 b){u64 d;asm("add.rn.f32x2 %0,%1,%2;":"=l"(d):"l"(a),"l"(b));return d;}
DEVFN float tanha(float x){float y;asm("tanh.approx.f32 %0,%1;":"=f"(y):"f"(x));return y;}
DEVFN float sigt(float x){ return fmaf(tanha(0.5f*x),0.5f,0.5f); }

DEVFN float eluf(float x){ return x>0.f ? x : (__expf(x)-1.f); }
DEVFN void softmax8(const float* gp, float* om){
  float g[8];
#pragma unroll
  for(int e=0;e<8;e++) g[e]=gp[e];
  float m=g[0];
#pragma unroll
  for(int e=1;e<8;e++) m=fmaxf(m,g[e]);
  float s=0.f;
#pragma unroll
  for(int e=0;e<8;e++){ om[e]=__expf(g[e]-m); s+=om[e]; }
  float inv=__fdividef(1.f,s);
#pragma unroll
  for(int e=0;e<8;e++) om[e]*=inv;
}

// ---------------- K1: gate GRU scan (blocks 0..31, 2 worker warps) + GEMM ----
// (unchanged from R12 — measured working)
__global__ __launch_bounds__(256) void k1_gate_gemm(Params P)
{
  __shared__ __align__(16) float h1r[2][4][8];
  __shared__ __align__(16) float h2r[2][4][8];
  __shared__ __align__(16) float sxg[4][129*3];      // staged gate inputs (+pad)
  __shared__ float Xs[64][32];
  __shared__ float Ws[32][128];

  const int bid=blockIdx.x, tid=threadIdx.x;
  if (bid < 32) {
    if (bid==0 && tid>=64 && tid<128) g_stats[tid-64]=0.f;  // fresh each replay
    const bool worker = tid<64;
    const int wp=tid>>5;                // 0 or 1 for workers
    const int lane=tid&31;
    const int sw=lane>>3, j=lane&7;
    const int s=bid*4+sw;

    // stage x with all 256 threads: 4 seqs x 129 steps x 3 feats (pad zeros)
#pragma unroll
    for (int ss=0; ss<4; ss++){
      const int sg=bid*4+ss, bb=sg&63;
      const float* Tb=((sg<64)?P.Local:P.Remote)+(size_t)bb*128*132+128;
      for (int tt=tid; tt<129; tt+=256){
        float a=0.f,b2=0.f,c=0.f;
        if (tt<128){ const float* p=Tb+(size_t)tt*132; a=p[0]; b2=p[1]; c=p[2]; }
        sxg[ss][tt*3+0]=a; sxg[ss][tt*3+1]=b2; sxg[ss][tt*3+2]=c;
      }
    }

    // per-warp weights (workers only)
    u64 Wr[4],Wz[4],Wn[4], Vr[4],Vz[4],Vn[4];
    u64 brp=0,bzp=0,bnp=0, crp=0,czp=0,cnp=0;
    float wxr0=0,wxr1=0,wxr2=0,wxz0=0,wxz1=0,wxz2=0,wxn0=0,wxn1=0,wxn2=0;
    float bxr=0,bxz=0,bxn=0, bhr_s=0,bhz_s=0,bhn_s=0;
#pragma unroll
    for(int k=0;k<4;k++){Wr[k]=0;Wz[k]=0;Wn[k]=0;Vr[k]=0;Vz[k]=0;Vn[k]=0;}
    if (worker && wp==0){
      wxr0=P.gWih0[j*3+0];wxr1=P.gWih0[j*3+1];wxr2=P.gWih0[j*3+2];
      wxz0=P.gWih0[(8+j)*3+0];wxz1=P.gWih0[(8+j)*3+1];wxz2=P.gWih0[(8+j)*3+2];
      wxn0=P.gWih0[(16+j)*3+0];wxn1=P.gWih0[(16+j)*3+1];wxn2=P.gWih0[(16+j)*3+2];
      bxr=P.gbih0[j]; bxz=P.gbih0[8+j]; bxn=P.gbih0[16+j];
#pragma unroll
      for(int k=0;k<4;k++){
        Wr[k]=pk2(P.gWhh0[j*8+2*k],P.gWhh0[j*8+2*k+1]);
        Wz[k]=pk2(P.gWhh0[(8+j)*8+2*k],P.gWhh0[(8+j)*8+2*k+1]);
        Wn[k]=pk2(P.gWhh0[(16+j)*8+2*k],P.gWhh0[(16+j)*8+2*k+1]);
      }
      brp=pk2(P.gbhh0[j],0.f); bzp=pk2(P.gbhh0[8+j],0.f); bnp=pk2(P.gbhh0[16+j],0.f);
      bhr_s=P.gbhh0[j]; bhz_s=P.gbhh0[8+j]; bhn_s=P.gbhh0[16+j];
    } else if (worker){
#pragma unroll
      for(int k=0;k<4;k++){
        Wr[k]=pk2(P.gWih1[j*8+2*k],P.gWih1[j*8+2*k+1]);
        Wz[k]=pk2(P.gWih1[(8+j)*8+2*k],P.gWih1[(8+j)*8+2*k+1]);
        Wn[k]=pk2(P.gWih1[(16+j)*8+2*k],P.gWih1[(16+j)*8+2*k+1]);
        Vr[k]=pk2(P.gWhh1[j*8+2*k],P.gWhh1[j*8+2*k+1]);
        Vz[k]=pk2(P.gWhh1[(8+j)*8+2*k],P.gWhh1[(8+j)*8+2*k+1]);
        Vn[k]=pk2(P.gWhh1[(16+j)*8+2*k],P.gWhh1[(16+j)*8+2*k+1]);
      }
      brp=pk2(P.gbih1[j],0.f); bzp=pk2(P.gbih1[8+j],0.f); bnp=pk2(P.gbih1[16+j],0.f);
      crp=pk2(P.gbhh1[j],0.f); czp=pk2(P.gbhh1[8+j],0.f); cnp=pk2(P.gbhh1[16+j],0.f);
    }
    __syncthreads();   // staging visible

    float h=0.f;
    if (worker && wp==0){   // prologue: h1(0), h1_prev=0 -> hh matvec = bias
      float x0=sxg[sw][0],x1=sxg[sw][1],x2=sxg[sw][2];
      float ir=fmaf(wxr2,x2,fmaf(wxr1,x1,fmaf(wxr0,x0,bxr)));
      float iz=fmaf(wxz2,x2,fmaf(wxz1,x1,fmaf(wxz0,x0,bxz)));
      float in_=fmaf(wxn2,x2,fmaf(wxn1,x1,fmaf(wxn0,x0,bxn)));
      float r=sigt(ir+bhr_s), z=sigt(iz+bhz_s), n=tanha(fmaf(r,bhn_s,in_));
      h=fmaf(z,-n,n);
    }
    float* Gout = g_G + (size_t)s*128*8 + j;

    for (int t=0;t<128;t++){
      const int buf=t&1;
      if (worker){ if (wp==0) h1r[buf][sw][j]=h; else h2r[buf][sw][j]=h; }
      __syncthreads();
      if (worker && wp==0){
        const ulonglong2* p1=(const ulonglong2*)&h1r[buf][sw][0];
        ulonglong2 v0=p1[0], v1=p1[1];
        u64 A1[4]={v0.x,v0.y,v1.x,v1.y};
        const float* xq=&sxg[sw][(t+1)*3];
        float nx0=xq[0],nx1=xq[1],nx2=xq[2];
        u64 hr=brp,hz=bzp,hn=bnp;
#pragma unroll
        for(int k=0;k<4;k++){ hr=fma2(Wr[k],A1[k],hr); hz=fma2(Wz[k],A1[k],hz); hn=fma2(Wn[k],A1[k],hn); }
        float ir=fmaf(wxr2,nx2,fmaf(wxr1,nx1,fmaf(wxr0,nx0,bxr)));
        float iz=fmaf(wxz2,nx2,fmaf(wxz1,nx1,fmaf(wxz0,nx0,bxz)));
        float in_=fmaf(wxn2,nx2,fmaf(wxn1,nx1,fmaf(wxn0,nx0,bxn)));
        float r1=sigt(ir+hadd2(hr));
        float z1=sigt(iz+hadd2(hz));
        float n1=tanha(fmaf(r1,hadd2(hn),in_));
        h=fmaf(z1,h-n1,n1);
      } else if (worker){
        const ulonglong2* p1=(const ulonglong2*)&h1r[buf][sw][0];
        const ulonglong2* p2=(const ulonglong2*)&h2r[buf][sw][0];
        ulonglong2 v10=p1[0], v11=p1[1], v20=p2[0], v21=p2[1];
        u64 A1[4]={v10.x,v10.y,v11.x,v11.y};
        u64 A2[4]={v20.x,v20.y,v21.x,v21.y};
        u64 i2r=brp,i2z=bzp,i2n=bnp, q2r=crp,q2z=czp,q2n=cnp;
#pragma unroll
        for(int k=0;k<4;k++){
          i2r=fma2(Wr[k],A1[k],i2r); i2z=fma2(Wz[k],A1[k],i2z); i2n=fma2(Wn[k],A1[k],i2n);
          q2r=fma2(Vr[k],A2[k],q2r); q2z=fma2(Vz[k],A2[k],q2z); q2n=fma2(Vn[k],A2[k],q2n);
        }
        float r2=sigt(hadd2(add2(i2r,q2r)));
        float z2=sigt(hadd2(add2(i2z,q2z)));
        float n2=tanha(fmaf(r2,hadd2(q2n),hadd2(i2n)));
        h=fmaf(z2,h-n2,n2);
        Gout[(size_t)t*8]=h;
      }
    }
    return;
  }
  // expert-1 GEMM: 64 rows x 128 cols per block
  {
    const int gb=bid-32, row0=gb*64;
    const int cg=tid&31, rg=tid>>5;
    float acc[8][4];
#pragma unroll
    for(int i=0;i<8;i++){acc[i][0]=0;acc[i][1]=0;acc[i][2]=0;acc[i][3]=0;}
    for (int kb=0;kb<128;kb+=32){
      for (int q=tid;q<512;q+=256){
        int r=q>>3, f4=q&7, row=row0+r;
        const float* xp=(row<8192)? (P.Local+(size_t)row*132) : (P.Remote+(size_t)(row-8192)*132);
        *(float4*)&Xs[r][f4*4] = *(const float4*)(xp+kb+f4*4);
      }
      for (int q=tid;q<1024;q+=256){
        int kk=q>>5, c=(q&31)*4, e=c>>4, h0=c&15;
        *(float4*)&Ws[kk][c] = *(const float4*)(P.aew1+(size_t)e*2048+(size_t)(kb+kk)*16+h0);
      }
      __syncthreads();
#pragma unroll
      for (int kk=0;kk<32;kk++){
        float4 w=*(float4*)&Ws[kk][cg*4];
#pragma unroll
        for(int i=0;i<8;i++){
          float x=Xs[rg*8+i][kk];
          acc[i][0]=fmaf(x,w.x,acc[i][0]); acc[i][1]=fmaf(x,w.y,acc[i][1]);
          acc[i][2]=fmaf(x,w.z,acc[i][2]); acc[i][3]=fmaf(x,w.w,acc[i][3]);
        }
      }
      __syncthreads();
    }
#pragma unroll
    for(int i=0;i<8;i++)
      *(float4*)&g_P[(size_t)(row0+rg*8+i)*128+cg*4] =
        make_float4(acc[i][0],acc[i][1],acc[i][2],acc[i][3]);
  }
}

// ---------------- K2: gated mix + BN stats (softmax computed once per row) ---
__global__ __launch_bounds__(256) void k2_mix(Params P)
{
  __shared__ float som[128][8];
  const int tid=threadIdx.x;
  const int rowbase=blockIdx.x*128;
  const int call=rowbase>>13;
  const int hh=tid&15;
  if (tid<128){
    const int rr=(rowbase+tid)&8191, bb=rr>>7, w=rr&127;
    float om[8]; softmax8(g_G+((size_t)(call*64+bb)*128+w)*8, om);
#pragma unroll
    for(int e=0;e<8;e++) som[tid][e]=om[e];
  }
  float b1v[8];
#pragma unroll
  for(int e=0;e<8;e++) b1v[e]=P.aeb1[e*16+hh];
  __syncthreads();
  float s1=0.f,s2=0.f;
  for (int pass=0;pass<8;pass++){
    const int lr=pass*16+(tid>>4);
    const int row=rowbase+lr;
    const float* pp=g_P+(size_t)row*128+hh;
    float h=0.f;
#pragma unroll
    for(int e=0;e<8;e++) h=fmaf(som[lr][e], pp[e*16]+b1v[e], h);
    g_H[(size_t)row*16+hh]=h;
    s1+=h; s2=fmaf(h,h,s2);
  }
  __shared__ float red[256];
  red[tid]=s1; __syncthreads();
  for(int off=128;off>=16;off>>=1){ if(tid<off) red[tid]+=red[tid+off]; __syncthreads(); }
  if(tid<16) atomicAdd(&g_stats[call*32+tid], red[tid]);
  __syncthreads();
  red[tid]=s2; __syncthreads();
  for(int off=128;off>=16;off>>=1){ if(tid<off) red[tid]+=red[tid+off]; __syncthreads(); }
  if(tid<16) atomicAdd(&g_stats[call*32+16+tid], red[tid]);
}

// ---------------- K3: BN+ELU+expert2; Z=ZL+ZR; mixer input proj (f32x2) -----
__global__ __launch_bounds__(256) void k3_z(Params P)
{
  __shared__ __align__(16) float sw2[2048];
  __shared__ __align__(16) float sb2[128];
  __shared__ __align__(16) float sWm[768];
  __shared__ float sbm[48], sg[16], sbt[16];
  __shared__ float smean[32], srstd[32];
  __shared__ float zbuf[256*17];
  const int tid=threadIdx.x;
  for(int i=tid;i<2048;i+=256) sw2[i]=P.aew2[i];
  for(int i=tid;i<768;i+=256)  sWm[i]=P.mWih0[i];
  if(tid<128) sb2[tid]=P.aeb2[tid];
  if(tid<48)  sbm[tid]=P.mbih0[tid];
  if(tid<16){ sg[tid]=P.aeg[tid]; sbt[tid]=P.aebt[tid]; }
  if(tid<32){
    int c=tid>>4, hh=tid&15;
    float s1=g_stats[c*32+hh], s2=g_stats[c*32+16+hh];
    float m=s1*(1.f/8192.f), v=s2*(1.f/8192.f)-m*m;
    smean[tid]=m; srstd[tid]=rsqrtf(v+1e-5f);
  }
  __syncthreads();
  const int p=blockIdx.x*128+(tid&127);
  const int call=tid>>7;
  const int b=p>>7, w=p&127;
  const int row=call*8192+p;
  const float* gp=g_G+((size_t)(call*64+b)*128+w)*8;
  float om[8]; softmax8(gp,om);
  float a[16];
#pragma unroll
  for(int hh=0;hh<16;hh++){
    float h=g_H[(size_t)row*16+hh];
    a[hh]=eluf(sg[hh]*(h-smean[call*16+hh])*srstd[call*16+hh]+sbt[hh]);
  }
  u64 ap[16];
#pragma unroll
  for(int hh=0;hh<16;hh++) ap[hh]=pk2(a[hh],a[hh]);
  const u64* sw2p=(const u64*)sw2;
  const u64* sb2p=(const u64*)sb2;
  u64 zp[8];
#pragma unroll
  for(int o2=0;o2<8;o2++) zp[o2]=0ull;
#pragma unroll
  for(int e=0;e<8;e++){
    u64 wep=pk2(om[e],om[e]);
    u64 acc[8];
#pragma unroll
    for(int o2=0;o2<8;o2++) acc[o2]=sb2p[e*8+o2];
#pragma unroll
    for(int hh=0;hh<16;hh++){
#pragma unroll
      for(int o2=0;o2<8;o2++) acc[o2]=fma2(ap[hh], sw2p[e*128+hh*8+o2], acc[o2]);
    }
#pragma unroll
    for(int o2=0;o2<8;o2++) zp[o2]=fma2(wep, acc[o2], zp[o2]);
  }
#pragma unroll
  for(int o2=0;o2<8;o2++){
    float lo,hi; up2(zp[o2],lo,hi);
    zbuf[tid*17+2*o2]=lo; zbuf[tid*17+2*o2+1]=hi;
  }
  __syncthreads();
  if(tid<128){
    const int pp=blockIdx.x*128+tid;
    u64 Zp[8];
#pragma unroll
    for(int o2=0;o2<8;o2++)
      Zp[o2]=pk2(zbuf[tid*17+2*o2]+zbuf[(tid+128)*17+2*o2],
                 zbuf[tid*17+2*o2+1]+zbuf[(tid+128)*17+2*o2+1]);
    const u64* sWmp=(const u64*)sWm;
    float* xo=g_XW0+(size_t)pp*48;
#pragma unroll
    for(int i=0;i<48;i++){
      u64 acc=0ull;
#pragma unroll
      for(int o2=0;o2<8;o2++) acc=fma2(Zp[o2], sWmp[i*8+o2], acc);
      xo[i]=sbm[i]+hadd2(acc);
    }
  }
}

// ---------------- K4: mixer GRU scan (2 warps pipelined, 32-lane k-split) ----
// lanes j and j+16 each own half the k-dim (4 packed u64); combine partial
// dots with shfl_xor(16). warp0 = layer1, warp1 = layer2 one step behind.
__global__ __launch_bounds__(64,1) void k4_mgru(Params P)
{
  __shared__ __align__(16) float sx[129*48];        // staged inputs (+pad step)
  __shared__ __align__(16) float h1r[2][16];
  __shared__ __align__(16) float h2r[2][16];
  const int tid=threadIdx.x;
  const int wp=tid>>5;
  const int lane=tid&31;
  const int j=lane&15;
  const int half=lane>>4;        // which k-half this lane owns
  const int kb=half*8;           // k base (elements)
  const int s=blockIdx.x;

  {
    const float4* src=(const float4*)(g_XW0+(size_t)s*6144);
    float4* dst=(float4*)sx;
    for(int q=tid;q<1536;q+=64) dst[q]=src[q];
    if(tid<12) dst[1536+tid]=make_float4(0.f,0.f,0.f,0.f);  // pad t=128
  }

  u64 Wr[4],Wz[4],Wn[4], Vr[4],Vz[4],Vn[4];
  u64 brp=0,bzp=0,bnp=0, crp=0,czp=0,cnp=0;
  float b0r_s=0,b0z_s=0,b0n_s=0;
#pragma unroll
  for(int k=0;k<4;k++){Wr[k]=0;Wz[k]=0;Wn[k]=0;Vr[k]=0;Vz[k]=0;Vn[k]=0;}
  if (wp==0){
#pragma unroll
    for(int k=0;k<4;k++){
      Wr[k]=pk2(P.mWhh0[j*16+kb+2*k],P.mWhh0[j*16+kb+2*k+1]);
      Wz[k]=pk2(P.mWhh0[(16+j)*16+kb+2*k],P.mWhh0[(16+j)*16+kb+2*k+1]);
      Wn[k]=pk2(P.mWhh0[(32+j)*16+kb+2*k],P.mWhh0[(32+j)*16+kb+2*k+1]);
    }
    if (half==0){ brp=pk2(P.mbhh0[j],0.f); bzp=pk2(P.mbhh0[16+j],0.f); bnp=pk2(P.mbhh0[32+j],0.f); }
    b0r_s=P.mbhh0[j]; b0z_s=P.mbhh0[16+j]; b0n_s=P.mbhh0[32+j];
  } else {
#pragma unroll
    for(int k=0;k<4;k++){
      Wr[k]=pk2(P.mWih1[j*16+kb+2*k],P.mWih1[j*16+kb+2*k+1]);
      Wz[k]=pk2(P.mWih1[(16+j)*16+kb+2*k],P.mWih1[(16+j)*16+kb+2*k+1]);
      Wn[k]=pk2(P.mWih1[(32+j)*16+kb+2*k],P.mWih1[(32+j)*16+kb+2*k+1]);
      Vr[k]=pk2(P.mWhh1[j*16+kb+2*k],P.mWhh1[j*16+kb+2*k+1]);
      Vz[k]=pk2(P.mWhh1[(16+j)*16+kb+2*k],P.mWhh1[(16+j)*16+kb+2*k+1]);
      Vn[k]=pk2(P.mWhh1[(32+j)*16+kb+2*k],P.mWhh1[(32+j)*16+kb+2*k+1]);
    }
    if (half==0){
      brp=pk2(P.mbih1[j],0.f); bzp=pk2(P.mbih1[16+j],0.f); bnp=pk2(P.mbih1[32+j],0.f);
      crp=pk2(P.mbhh1[j],0.f); czp=pk2(P.mbhh1[16+j],0.f); cnp=pk2(P.mbhh1[32+j],0.f);
    }
  }
  __syncthreads();   // staging visible

  float h=0.f;
  if (wp==0){   // prologue: h1(0) with h1_prev = 0 (both halves compute same)
    float xr=sx[j], xz=sx[16+j], xn=sx[32+j];
    float r=sigt(xr+b0r_s), z=sigt(xz+b0z_s), n=tanha(fmaf(r,b0n_s,xn));
    h=fmaf(z,-n,n);
  }

  for (int t=0;t<128;t++){
    const int buf=t&1;
    if (lane<16){ if (wp==0) h1r[buf][j]=h; else h2r[buf][j]=h; }
    __syncthreads();
    const ulonglong2* p1=(const ulonglong2*)&h1r[buf][0];
    ulonglong2 va=p1[half*2], vb=p1[half*2+1];
    u64 A1[4]={va.x,va.y,vb.x,vb.y};
    if (wp==0){
      const float* xq=&sx[(t+1)*48];
      float nxr=xq[j], nxz=xq[16+j], nxn=xq[32+j];
      u64 hr=brp,hz=bzp,hn=bnp;
#pragma unroll
      for(int k=0;k<4;k++){ hr=fma2(Wr[k],A1[k],hr); hz=fma2(Wz[k],A1[k],hz); hn=fma2(Wn[k],A1[k],hn); }
      float hrs=hadd2(hr); hrs+=__shfl_xor_sync(0xffffffffu,hrs,16);
      float hzs=hadd2(hz); hzs+=__shfl_xor_sync(0xffffffffu,hzs,16);
      float hns=hadd2(hn); hns+=__shfl_xor_sync(0xffffffffu,hns,16);
      float r1=sigt(nxr+hrs);
      float z1=sigt(nxz+hzs);
      float n1=tanha(fmaf(r1,hns,nxn));
      h=fmaf(z1,h-n1,n1);
    } else {
      const ulonglong2* p2=(const ulonglong2*)&h2r[buf][0];
      ulonglong2 vc=p2[half*2], vd=p2[half*2+1];
      u64 A2[4]={vc.x,vc.y,vd.x,vd.y};
      u64 i2r=brp,i2z=bzp,i2n=bnp, q2r=crp,q2z=czp,q2n=cnp;
#pragma unroll
      for(int k=0;k<4;k++){
        i2r=fma2(Wr[k],A1[k],i2r); i2z=fma2(Wz[k],A1[k],i2z); i2n=fma2(Wn[k],A1[k],i2n);
        q2r=fma2(Vr[k],A2[k],q2r); q2z=fma2(Vz[k],A2[k],q2z); q2n=fma2(Vn[k],A2[k],q2n);
      }
      float irs=hadd2(add2(i2r,q2r)); irs+=__shfl_xor_sync(0xffffffffu,irs,16);
      float izs=hadd2(add2(i2z,q2z)); izs+=__shfl_xor_sync(0xffffffffu,izs,16);
      float ins=hadd2(i2n); ins+=__shfl_xor_sync(0xffffffffu,ins,16);
      float qns=hadd2(q2n); qns+=__shfl_xor_sync(0xffffffffu,qns,16);
      float r2=sigt(irs);
      float z2=sigt(izs);
      float n2=tanha(fmaf(r2,qns,ins));
      h=fmaf(z2,h-n2,n2);
    }
  }
  if (wp==1 && lane<16) g_HF[s*16+j]=h;   // warp1 half0 holds h2(127)
}

// ---------------- K5a: decoder hidden + BN + ELU; export C and om ----------
__global__ __launch_bounds__(1024) void k5a_dec(Params P)
{
  __shared__ float om_s[64*8], x_s[64*17], a_s[64*16], ms[16], rs[16];
  __shared__ __align__(16) float sW1[2176];
  __shared__ float sB1[128];
  const int tid=threadIdx.x;
  const int b=tid>>4, hh=tid&15;
  for(int i=tid;i<2176;i+=1024) sW1[i]=P.mdw1[i];
  if (tid<128) sB1[tid]=P.mdb1[tid];
  if (tid<64){
    const float* gp=g_G+((size_t)(64+tid)*128+127)*8;
    float om[8]; softmax8(gp,om);
#pragma unroll
    for(int e=0;e<8;e++) om_s[tid*8+e]=om[e];
    x_s[tid*17+16]=P.Remote[(size_t)tid*128*132+127*132+131];
  }
  x_s[b*17+hh]=g_HF[b*16+hh];
  __syncthreads();
  {
    float h=0.f;
#pragma unroll
    for(int e=0;e<8;e++){
      float acc=sB1[e*16+hh];
#pragma unroll
      for(int i=0;i<17;i++) acc=fmaf(x_s[b*17+i], sW1[e*272+i*16+hh], acc);
      h=fmaf(om_s[b*8+e],acc,h);
    }
    a_s[b*16+hh]=h;
  }
  __syncthreads();
  if (tid<16){
    float s1=0.f,s2=0.f;
    for(int bb=0;bb<64;bb++){ float v=a_s[bb*16+tid]; s1+=v; s2=fmaf(v,v,s2); }
    float m=s1*(1.f/64.f), v=s2*(1.f/64.f)-m*m;
    ms[tid]=m; rs[tid]=rsqrtf(v+1e-5f);
  }
  __syncthreads();
  {
    float h=a_s[b*16+hh];
    a_s[b*16+hh]=eluf(P.mdg[hh]*(h-ms[hh])*rs[hh]+P.mdbt[hh]);
  }
  __syncthreads();
  // export C[b][e*16+k] = om[b][e]*a[b][k]  and om
  for (int q=tid;q<8192;q+=1024){
    int bb=q>>7, m=q&127, e=m>>4, k=m&15;
    g_C[q]=om_s[bb*8+e]*a_s[bb*16+k];
  }
  if (tid<512) g_OMd[tid]=om_s[tid];
}

// ---------------- K5b: decoder output GEMM out = C @ mdw2_v + om.b2 --------
__global__ __launch_bounds__(256) void k5b_dec(Params P)
{
  __shared__ float sC[2][128], sOM[2][8];
  const int tid=threadIdx.x;
  const int b0=blockIdx.x*2;
  sC[tid>>7][tid&127]=g_C[(size_t)b0*128+tid];
  if (tid<16) sOM[tid>>3][tid&7]=g_OMd[b0*8+tid];
  __syncthreads();
  const int lb=tid>>7, o=tid&127;
  float acc=0.f;
#pragma unroll 4
  for (int m=0;m<128;m++) acc=fmaf(sC[lb][m], P.mdw2[(size_t)m*128+o], acc);
#pragma unroll
  for (int e=0;e<8;e++) acc=fmaf(sOM[lb][e], P.mdb2[e*128+o], acc);
  P.out[(size_t)(b0+lb)*128+o]=acc;
}

extern "C" void kernel_launch(void* const* d_in, const int* in_sizes, int n_in,
                              void* d_out, int out_size)
{
  Params P;
  const float** f = (const float**)d_in;
  P.Local=f[0]; P.Remote=f[1];
  P.gWih0=f[2]; P.gWhh0=f[3]; P.gbih0=f[4]; P.gbhh0=f[5];
  P.gWih1=f[6]; P.gWhh1=f[7]; P.gbih1=f[8]; P.gbhh1=f[9];
  if (in_sizes[10] == 16384) {
    P.aew1=f[10]; P.aeb1=f[11]; P.aew2=f[12]; P.aeb2=f[13]; P.aeg=f[14]; P.aebt=f[15];
    P.mdw1=f[16]; P.mdb1=f[17]; P.mdw2=f[18]; P.mdb2=f[19]; P.mdg=f[20]; P.mdbt=f[21];
    P.mWih0=f[22]; P.mWhh0=f[23]; P.mbih0=f[24]; P.mbhh0=f[25];
    P.mWih1=f[26]; P.mWhh1=f[27]; P.mbih1=f[28]; P.mbhh1=f[29];
  } else {
    P.mWih0=f[10]; P.mWhh0=f[11]; P.mbih0=f[12]; P.mbhh0=f[13];
    P.mWih1=f[14]; P.mWhh1=f[15]; P.mbih1=f[16]; P.mbhh1=f[17];
    P.aew1=f[18]; P.aeb1=f[19]; P.aew2=f[20]; P.aeb2=f[21]; P.aeg=f[22]; P.aebt=f[23];
    P.mdw1=f[24]; P.mdb1=f[25]; P.mdw2=f[26]; P.mdb2=f[27]; P.mdg=f[28]; P.mdbt=f[29];
  }
  P.out=(float*)d_out;

  k1_gate_gemm<<<288,256>>>(P);
  k2_mix<<<128,256>>>(P);
  k3_z<<<64,256>>>(P);
  k4_mgru<<<64,64>>>(P);
  k5a_dec<<<1,1024>>>(P);
  k5b_dec<<<32,256>>>(P);
}

// round 15
// speedup vs baseline: 1.2603x; 1.2603x over previous
#include <cuda_runtime.h>
#include <math.h>

// E=8 A=128 TGT=3 HID=16 OUT=128 B=64 W=128 F=132
struct Params {
  const float *Local, *Remote;
  const float *gWih0,*gWhh0,*gbih0,*gbhh0,*gWih1,*gWhh1,*gbih1,*gbhh1;
  const float *aew1,*aeb1,*aew2,*aeb2,*aeg,*aebt;
  const float *mdw1,*mdb1,*mdw2,*mdb2,*mdg,*mdbt;
  const float *mWih0,*mWhh0,*mbih0,*mbhh0,*mWih1,*mWhh1,*mbih1,*mbhh1;
  float* out;
};

__device__ __align__(16) float g_G[128*128*8];   // gate GRU hidden (pre-softmax) [seq][t][8]
__device__ __align__(16) float g_P[16384*128];   // expert-1 GEMM result
__device__ __align__(16) float g_H[16384*16];    // mixed hidden (pre-BN)
__device__             float g_stats[64];        // [call*32 + (sum16|sumsq16)]
__device__ __align__(16) float g_XW0[8192*48];   // mixer layer0 input projection (incl. bih0)
__device__ __align__(16) float g_HF[64*16];      // mixer final hidden
__device__ __align__(16) float g_C[64*128];      // decoder: om (x) a
__device__ __align__(16) float g_OMd[64*8];      // decoder gates

#define DEVFN __device__ __forceinline__
typedef unsigned long long u64;

DEVFN u64 pk2(float lo,float hi){u64 r;asm("mov.b64 %0,{%1,%2};":"=l"(r):"f"(lo),"f"(hi));return r;}
DEVFN float hadd2(u64 v){float lo,hi;asm("mov.b64 {%0,%1},%2;":"=f"(lo),"=f"(hi):"l"(v));return lo+hi;}
DEVFN void up2(u64 v,float&lo,float&hi){asm("mov.b64 {%0,%1},%2;":"=f"(lo),"=f"(hi):"l"(v));}
DEVFN u64 fma2(u64 a,u64 b,u64 c){u64 d;asm("fma.rn.f32x2 %0,%1,%2,%3;":"=l"(d):"l"(a),"l"(b),"l"(c));return d;}
DEVFN u64 add2(u64 a,u64 b){u64 d;asm("add.rn.f32x2 %0,%1,%2;":"=l"(d):"l"(a),"l"(b));return d;}
DEVFN float tanha(float x){float y;asm("tanh.approx.f32 %0,%1;":"=f"(y):"f"(x));return y;}
DEVFN float sigt(float x){ return fmaf(tanha(0.5f*x),0.5f,0.5f); }

DEVFN float eluf(float x){ return x>0.f ? x : (__expf(x)-1.f); }
DEVFN void softmax8(const float* gp, float* om){
  float g[8];
#pragma unroll
  for(int e=0;e<8;e++) g[e]=gp[e];
  float m=g[0];
#pragma unroll
  for(int e=1;e<8;e++) m=fmaxf(m,g[e]);
  float s=0.f;
#pragma unroll
  for(int e=0;e<8;e++){ om[e]=__expf(g[e]-m); s+=om[e]; }
  float inv=__fdividef(1.f,s);
#pragma unroll
  for(int e=0;e<8;e++) om[e]*=inv;
}

// ---------------- K1: gate GRU scan (blocks 0..31) + expert-1 GEMM ----------
// Gate blocks: warp0 = layer1, warp1 = layer2 one GROUP (4 steps) behind.
// h1 crosses warps via double-buffered group buffers; one __syncthreads per
// 4 steps. Zero-prefilled cells make t=0 branch-free (dot over 0s = bias).
__global__ __launch_bounds__(256) void k1_gate_gemm(Params P)
{
  __shared__ __align__(16) float h1g[2][4][4][8];   // [buf][u][seq][unit]
  __shared__ __align__(16) float h2sg[2][4][8];     // warp1 private scratch
  __shared__ __align__(16) float sxg[4][129*3];     // staged gate inputs
  __shared__ float Xs[64][32];
  __shared__ float Ws[32][128];

  const int bid=blockIdx.x, tid=threadIdx.x;
  if (bid < 32) {
    if (bid==0 && tid>=64 && tid<128) g_stats[tid-64]=0.f;  // fresh each replay
    const bool worker = tid<64;
    const int wp=tid>>5;
    const int lane=tid&31;
    const int sw=lane>>3, j=lane&7;
    const int s=bid*4+sw;

    // stage x with all 256 threads: 4 seqs x 128 steps x 3 feats
#pragma unroll
    for (int ss=0; ss<4; ss++){
      const int sg=bid*4+ss, bb=sg&63;
      const float* Tb=((sg<64)?P.Local:P.Remote)+(size_t)bb*128*132+128;
      for (int tt=tid; tt<128; tt+=256){
        const float* p=Tb+(size_t)tt*132;
        sxg[ss][tt*3+0]=p[0]; sxg[ss][tt*3+1]=p[1]; sxg[ss][tt*3+2]=p[2];
      }
    }
    if (tid<32) h1g[1][3][tid>>3][tid&7]=0.f;   // zero "previous" cell for g=0

    // per-warp weights (workers only)
    u64 Wr[4],Wz[4],Wn[4], Vr[4],Vz[4],Vn[4];
    u64 brp=0,bzp=0,bnp=0, crp=0,czp=0,cnp=0;
    float wxr0=0,wxr1=0,wxr2=0,wxz0=0,wxz1=0,wxz2=0,wxn0=0,wxn1=0,wxn2=0;
    float bxr=0,bxz=0,bxn=0;
#pragma unroll
    for(int k=0;k<4;k++){Wr[k]=0;Wz[k]=0;Wn[k]=0;Vr[k]=0;Vz[k]=0;Vn[k]=0;}
    if (worker && wp==0){
      wxr0=P.gWih0[j*3+0];wxr1=P.gWih0[j*3+1];wxr2=P.gWih0[j*3+2];
      wxz0=P.gWih0[(8+j)*3+0];wxz1=P.gWih0[(8+j)*3+1];wxz2=P.gWih0[(8+j)*3+2];
      wxn0=P.gWih0[(16+j)*3+0];wxn1=P.gWih0[(16+j)*3+1];wxn2=P.gWih0[(16+j)*3+2];
      bxr=P.gbih0[j]; bxz=P.gbih0[8+j]; bxn=P.gbih0[16+j];
#pragma unroll
      for(int k=0;k<4;k++){
        Wr[k]=pk2(P.gWhh0[j*8+2*k],P.gWhh0[j*8+2*k+1]);
        Wz[k]=pk2(P.gWhh0[(8+j)*8+2*k],P.gWhh0[(8+j)*8+2*k+1]);
        Wn[k]=pk2(P.gWhh0[(16+j)*8+2*k],P.gWhh0[(16+j)*8+2*k+1]);
      }
      brp=pk2(P.gbhh0[j],0.f); bzp=pk2(P.gbhh0[8+j],0.f); bnp=pk2(P.gbhh0[16+j],0.f);
    } else if (worker){
#pragma unroll
      for(int k=0;k<4;k++){
        Wr[k]=pk2(P.gWih1[j*8+2*k],P.gWih1[j*8+2*k+1]);
        Wz[k]=pk2(P.gWih1[(8+j)*8+2*k],P.gWih1[(8+j)*8+2*k+1]);
        Wn[k]=pk2(P.gWih1[(16+j)*8+2*k],P.gWih1[(16+j)*8+2*k+1]);
        Vr[k]=pk2(P.gWhh1[j*8+2*k],P.gWhh1[j*8+2*k+1]);
        Vz[k]=pk2(P.gWhh1[(8+j)*8+2*k],P.gWhh1[(8+j)*8+2*k+1]);
        Vn[k]=pk2(P.gWhh1[(16+j)*8+2*k],P.gWhh1[(16+j)*8+2*k+1]);
      }
      brp=pk2(P.gbih1[j],0.f); bzp=pk2(P.gbih1[8+j],0.f); bnp=pk2(P.gbih1[16+j],0.f);
      crp=pk2(P.gbhh1[j],0.f); czp=pk2(P.gbhh1[8+j],0.f); cnp=pk2(P.gbhh1[16+j],0.f);
    }
    __syncthreads();   // staging + zero-prefill visible

    float h=0.f;
    float* Gout = g_G + (size_t)s*128*8 + j;

    for (int g=0; g<33; g++){
      if (worker && wp==0 && g<32){
        const int buf=g&1;
#pragma unroll
        for (int u=0; u<4; u++){
          const int t=4*g+u;             // computing h1(t) from h1(t-1)
          const float* srcp=(u==0)? &h1g[buf^1][3][sw][0] : &h1g[buf][u-1][sw][0];
          const ulonglong2* p1=(const ulonglong2*)srcp;
          ulonglong2 v0=p1[0], v1=p1[1];
          u64 A1[4]={v0.x,v0.y,v1.x,v1.y};
          u64 hr=brp,hz=bzp,hn=bnp;
#pragma unroll
          for(int k=0;k<4;k++){ hr=fma2(Wr[k],A1[k],hr); hz=fma2(Wz[k],A1[k],hz); hn=fma2(Wn[k],A1[k],hn); }
          const float* xq=&sxg[sw][t*3];
          float x0=xq[0],x1=xq[1],x2=xq[2];
          float ir=fmaf(wxr2,x2,fmaf(wxr1,x1,fmaf(wxr0,x0,bxr)));
          float iz=fmaf(wxz2,x2,fmaf(wxz1,x1,fmaf(wxz0,x0,bxz)));
          float in_=fmaf(wxn2,x2,fmaf(wxn1,x1,fmaf(wxn0,x0,bxn)));
          float r1=sigt(ir+hadd2(hr));
          float z1=sigt(iz+hadd2(hz));
          float n1=tanha(fmaf(r1,hadd2(hn),in_));
          h=fmaf(z1,h-n1,n1);
          h1g[buf][u][sw][j]=h;
          __syncwarp();
        }
      } else if (worker && wp==1 && g>=1){
        const int buf=(g-1)&1;
#pragma unroll
        for (int u=0; u<4; u++){
          const int t=4*(g-1)+u;         // computing h2(t)
          h2sg[u&1][sw][j]=h;            // h2(t-1); h=0 at t=0 -> bias-only
          __syncwarp();
          const ulonglong2* p1=(const ulonglong2*)&h1g[buf][u][sw][0];
          const ulonglong2* p2=(const ulonglong2*)&h2sg[u&1][sw][0];
          ulonglong2 v10=p1[0], v11=p1[1], v20=p2[0], v21=p2[1];
          u64 A1[4]={v10.x,v10.y,v11.x,v11.y};
          u64 A2[4]={v20.x,v20.y,v21.x,v21.y};
          u64 i2r=brp,i2z=bzp,i2n=bnp, q2r=crp,q2z=czp,q2n=cnp;
#pragma unroll
          for(int k=0;k<4;k++){
            i2r=fma2(Wr[k],A1[k],i2r); i2z=fma2(Wz[k],A1[k],i2z); i2n=fma2(Wn[k],A1[k],i2n);
            q2r=fma2(Vr[k],A2[k],q2r); q2z=fma2(Vz[k],A2[k],q2z); q2n=fma2(Vn[k],A2[k],q2n);
          }
          float r2=sigt(hadd2(add2(i2r,q2r)));
          float z2=sigt(hadd2(add2(i2z,q2z)));
          float n2=tanha(fmaf(r2,hadd2(q2n),hadd2(i2n)));
          h=fmaf(z2,h-n2,n2);
          Gout[(size_t)t*8]=h;
        }
      }
      __syncthreads();
    }
    return;
  }
  // expert-1 GEMM: 64 rows x 128 cols per block
  {
    const int gb=bid-32, row0=gb*64;
    const int cg=tid&31, rg=tid>>5;
    float acc[8][4];
#pragma unroll
    for(int i=0;i<8;i++){acc[i][0]=0;acc[i][1]=0;acc[i][2]=0;acc[i][3]=0;}
    for (int kb=0;kb<128;kb+=32){
      for (int q=tid;q<512;q+=256){
        int r=q>>3, f4=q&7, row=row0+r;
        const float* xp=(row<8192)? (P.Local+(size_t)row*132) : (P.Remote+(size_t)(row-8192)*132);
        *(float4*)&Xs[r][f4*4] = *(const float4*)(xp+kb+f4*4);
      }
      for (int q=tid;q<1024;q+=256){
        int kk=q>>5, c=(q&31)*4, e=c>>4, h0=c&15;
        *(float4*)&Ws[kk][c] = *(const float4*)(P.aew1+(size_t)e*2048+(size_t)(kb+kk)*16+h0);
      }
      __syncthreads();
#pragma unroll
      for (int kk=0;kk<32;kk++){
        float4 w=*(float4*)&Ws[kk][cg*4];
#pragma unroll
        for(int i=0;i<8;i++){
          float x=Xs[rg*8+i][kk];
          acc[i][0]=fmaf(x,w.x,acc[i][0]); acc[i][1]=fmaf(x,w.y,acc[i][1]);
          acc[i][2]=fmaf(x,w.z,acc[i][2]); acc[i][3]=fmaf(x,w.w,acc[i][3]);
        }
      }
      __syncthreads();
    }
#pragma unroll
    for(int i=0;i<8;i++)
      *(float4*)&g_P[(size_t)(row0+rg*8+i)*128+cg*4] =
        make_float4(acc[i][0],acc[i][1],acc[i][2],acc[i][3]);
  }
}

// ---------------- K2: gated mix + BN stats (softmax computed once per row) ---
__global__ __launch_bounds__(256) void k2_mix(Params P)
{
  __shared__ float som[128][8];
  const int tid=threadIdx.x;
  const int rowbase=blockIdx.x*128;
  const int call=rowbase>>13;
  const int hh=tid&15;
  if (tid<128){
    const int rr=(rowbase+tid)&8191, bb=rr>>7, w=rr&127;
    float om[8]; softmax8(g_G+((size_t)(call*64+bb)*128+w)*8, om);
#pragma unroll
    for(int e=0;e<8;e++) som[tid][e]=om[e];
  }
  float b1v[8];
#pragma unroll
  for(int e=0;e<8;e++) b1v[e]=P.aeb1[e*16+hh];
  __syncthreads();
  float s1=0.f,s2=0.f;
  for (int pass=0;pass<8;pass++){
    const int lr=pass*16+(tid>>4);
    const int row=rowbase+lr;
    const float* pp=g_P+(size_t)row*128+hh;
    float h=0.f;
#pragma unroll
    for(int e=0;e<8;e++) h=fmaf(som[lr][e], pp[e*16]+b1v[e], h);
    g_H[(size_t)row*16+hh]=h;
    s1+=h; s2=fmaf(h,h,s2);
  }
  __shared__ float red[256];
  red[tid]=s1; __syncthreads();
  for(int off=128;off>=16;off>>=1){ if(tid<off) red[tid]+=red[tid+off]; __syncthreads(); }
  if(tid<16) atomicAdd(&g_stats[call*32+tid], red[tid]);
  __syncthreads();
  red[tid]=s2; __syncthreads();
  for(int off=128;off>=16;off>>=1){ if(tid<off) red[tid]+=red[tid+off]; __syncthreads(); }
  if(tid<16) atomicAdd(&g_stats[call*32+16+tid], red[tid]);
}

// ---------------- K3: BN+ELU+expert2; Z=ZL+ZR; mixer input proj (f32x2) -----
__global__ __launch_bounds__(256) void k3_z(Params P)
{
  __shared__ __align__(16) float sw2[2048];
  __shared__ __align__(16) float sb2[128];
  __shared__ __align__(16) float sWm[768];
  __shared__ float sbm[48], sg[16], sbt[16];
  __shared__ float smean[32], srstd[32];
  __shared__ float zbuf[256*17];
  const int tid=threadIdx.x;
  for(int i=tid;i<2048;i+=256) sw2[i]=P.aew2[i];
  for(int i=tid;i<768;i+=256)  sWm[i]=P.mWih0[i];
  if(tid<128) sb2[tid]=P.aeb2[tid];
  if(tid<48)  sbm[tid]=P.mbih0[tid];
  if(tid<16){ sg[tid]=P.aeg[tid]; sbt[tid]=P.aebt[tid]; }
  if(tid<32){
    int c=tid>>4, hh=tid&15;
    float s1=g_stats[c*32+hh], s2=g_stats[c*32+16+hh];
    float m=s1*(1.f/8192.f), v=s2*(1.f/8192.f)-m*m;
    smean[tid]=m; srstd[tid]=rsqrtf(v+1e-5f);
  }
  __syncthreads();
  const int p=blockIdx.x*128+(tid&127);
  const int call=tid>>7;
  const int b=p>>7, w=p&127;
  const int row=call*8192+p;
  const float* gp=g_G+((size_t)(call*64+b)*128+w)*8;
  float om[8]; softmax8(gp,om);
  float a[16];
#pragma unroll
  for(int hh=0;hh<16;hh++){
    float h=g_H[(size_t)row*16+hh];
    a[hh]=eluf(sg[hh]*(h-smean[call*16+hh])*srstd[call*16+hh]+sbt[hh]);
  }
  u64 ap[16];
#pragma unroll
  for(int hh=0;hh<16;hh++) ap[hh]=pk2(a[hh],a[hh]);
  const u64* sw2p=(const u64*)sw2;
  const u64* sb2p=(const u64*)sb2;
  u64 zp[8];
#pragma unroll
  for(int o2=0;o2<8;o2++) zp[o2]=0ull;
#pragma unroll
  for(int e=0;e<8;e++){
    u64 wep=pk2(om[e],om[e]);
    u64 acc[8];
#pragma unroll
    for(int o2=0;o2<8;o2++) acc[o2]=sb2p[e*8+o2];
#pragma unroll
    for(int hh=0;hh<16;hh++){
#pragma unroll
      for(int o2=0;o2<8;o2++) acc[o2]=fma2(ap[hh], sw2p[e*128+hh*8+o2], acc[o2]);
    }
#pragma unroll
    for(int o2=0;o2<8;o2++) zp[o2]=fma2(wep, acc[o2], zp[o2]);
  }
#pragma unroll
  for(int o2=0;o2<8;o2++){
    float lo,hi; up2(zp[o2],lo,hi);
    zbuf[tid*17+2*o2]=lo; zbuf[tid*17+2*o2+1]=hi;
  }
  __syncthreads();
  if(tid<128){
    const int pp=blockIdx.x*128+tid;
    u64 Zp[8];
#pragma unroll
    for(int o2=0;o2<8;o2++)
      Zp[o2]=pk2(zbuf[tid*17+2*o2]+zbuf[(tid+128)*17+2*o2],
                 zbuf[tid*17+2*o2+1]+zbuf[(tid+128)*17+2*o2+1]);
    const u64* sWmp=(const u64*)sWm;
    float* xo=g_XW0+(size_t)pp*48;
#pragma unroll
    for(int i=0;i<48;i++){
      u64 acc=0ull;
#pragma unroll
      for(int o2=0;o2<8;o2++) acc=fma2(Zp[o2], sWmp[i*8+o2], acc);
      xo[i]=sbm[i]+hadd2(acc);
    }
  }
}

// ---------------- K4: mixer GRU scan (2 warps, grouped 4-step pipeline) ------
// warp0 = layer1, warp1 = layer2 one group behind. h1 crosses warps in
// double-buffered group buffers; one __syncthreads per 4 steps.
__global__ __launch_bounds__(64,1) void k4_mgru(Params P)
{
  __shared__ __align__(16) float sx[128*48];        // staged inputs
  __shared__ __align__(16) float h1g[2][4][16];     // [buf][u][unit]
  __shared__ __align__(16) float h2s[2][16];        // warp1 private scratch
  const int tid=threadIdx.x;
  const int wp=tid>>5;
  const int lane=tid&31;
  const int j=lane&15;
  const int s=blockIdx.x;

  {
    const float4* src=(const float4*)(g_XW0+(size_t)s*6144);
    float4* dst=(float4*)sx;
    for(int q=tid;q<1536;q+=64) dst[q]=src[q];
    if (tid<16) h1g[1][3][tid]=0.f;                 // zero "previous" cell
  }

  u64 Wr[8],Wz[8],Wn[8], Vr[8],Vz[8],Vn[8];
  u64 brp=0,bzp=0,bnp=0, crp=0,czp=0,cnp=0;
#pragma unroll
  for(int k=0;k<8;k++){Wr[k]=0;Wz[k]=0;Wn[k]=0;Vr[k]=0;Vz[k]=0;Vn[k]=0;}
  if (wp==0){
#pragma unroll
    for(int k=0;k<8;k++){
      Wr[k]=pk2(P.mWhh0[j*16+2*k],P.mWhh0[j*16+2*k+1]);
      Wz[k]=pk2(P.mWhh0[(16+j)*16+2*k],P.mWhh0[(16+j)*16+2*k+1]);
      Wn[k]=pk2(P.mWhh0[(32+j)*16+2*k],P.mWhh0[(32+j)*16+2*k+1]);
    }
    brp=pk2(P.mbhh0[j],0.f); bzp=pk2(P.mbhh0[16+j],0.f); bnp=pk2(P.mbhh0[32+j],0.f);
  } else {
#pragma unroll
    for(int k=0;k<8;k++){
      Wr[k]=pk2(P.mWih1[j*16+2*k],P.mWih1[j*16+2*k+1]);
      Wz[k]=pk2(P.mWih1[(16+j)*16+2*k],P.mWih1[(16+j)*16+2*k+1]);
      Wn[k]=pk2(P.mWih1[(32+j)*16+2*k],P.mWih1[(32+j)*16+2*k+1]);
      Vr[k]=pk2(P.mWhh1[j*16+2*k],P.mWhh1[j*16+2*k+1]);
      Vz[k]=pk2(P.mWhh1[(16+j)*16+2*k],P.mWhh1[(16+j)*16+2*k+1]);
      Vn[k]=pk2(P.mWhh1[(32+j)*16+2*k],P.mWhh1[(32+j)*16+2*k+1]);
    }
    brp=pk2(P.mbih1[j],0.f); bzp=pk2(P.mbih1[16+j],0.f); bnp=pk2(P.mbih1[32+j],0.f);
    crp=pk2(P.mbhh1[j],0.f); czp=pk2(P.mbhh1[16+j],0.f); cnp=pk2(P.mbhh1[32+j],0.f);
  }
  __syncthreads();   // staging + zero-prefill visible

  float h=0.f;
  for (int g=0; g<33; g++){
    if (wp==0 && g<32){
      const int buf=g&1;
#pragma unroll
      for (int u=0; u<4; u++){
        const int t=4*g+u;               // computing h1(t) from h1(t-1)
        const float* srcp=(u==0)? &h1g[buf^1][3][0] : &h1g[buf][u-1][0];
        const ulonglong2* p1=(const ulonglong2*)srcp;
        ulonglong2 v0=p1[0], v1=p1[1], v2=p1[2], v3=p1[3];
        u64 A1[8]={v0.x,v0.y,v1.x,v1.y,v2.x,v2.y,v3.x,v3.y};
        u64 hr=brp,hz=bzp,hn=bnp;
#pragma unroll
        for(int k=0;k<8;k++){ hr=fma2(Wr[k],A1[k],hr); hz=fma2(Wz[k],A1[k],hz); hn=fma2(Wn[k],A1[k],hn); }
        const float* xq=&sx[t*48];
        float nxr=xq[j], nxz=xq[16+j], nxn=xq[32+j];
        float r1=sigt(nxr+hadd2(hr));
        float z1=sigt(nxz+hadd2(hz));
        float n1=tanha(fmaf(r1,hadd2(hn),nxn));
        h=fmaf(z1,h-n1,n1);
        if (lane<16) h1g[buf][u][j]=h;
        __syncwarp();
      }
    } else if (wp==1 && g>=1){
      const int buf=(g-1)&1;
#pragma unroll
      for (int u=0; u<4; u++){
        if (lane<16) h2s[u&1][j]=h;      // h2(t-1); h=0 at t=0 -> bias-only
        __syncwarp();
        const ulonglong2* p1=(const ulonglong2*)&h1g[buf][u][0];
        const ulonglong2* p2=(const ulonglong2*)&h2s[u&1][0];
        ulonglong2 v10=p1[0], v11=p1[1], v12=p1[2], v13=p1[3];
        ulonglong2 v20=p2[0], v21=p2[1], v22=p2[2], v23=p2[3];
        u64 A1[8]={v10.x,v10.y,v11.x,v11.y,v12.x,v12.y,v13.x,v13.y};
        u64 A2[8]={v20.x,v20.y,v21.x,v21.y,v22.x,v22.y,v23.x,v23.y};
        u64 i2r=brp,i2z=bzp,i2n=bnp, q2r=crp,q2z=czp,q2n=cnp;
#pragma unroll
        for(int k=0;k<8;k++){
          i2r=fma2(Wr[k],A1[k],i2r); i2z=fma2(Wz[k],A1[k],i2z); i2n=fma2(Wn[k],A1[k],i2n);
          q2r=fma2(Vr[k],A2[k],q2r); q2z=fma2(Vz[k],A2[k],q2z); q2n=fma2(Vn[k],A2[k],q2n);
        }
        float r2=sigt(hadd2(add2(i2r,q2r)));
        float z2=sigt(hadd2(add2(i2z,q2z)));
        float n2=tanha(fmaf(r2,hadd2(q2n),hadd2(i2n)));
        h=fmaf(z2,h-n2,n2);
      }
    }
    __syncthreads();
  }
  if (wp==1 && lane<16) g_HF[s*16+j]=h;
}

// ---------------- K5a: decoder hidden + BN + ELU; export C and om ----------
__global__ __launch_bounds__(1024) void k5a_dec(Params P)
{
  __shared__ float om_s[64*8], x_s[64*17], a_s[64*16], ms[16], rs[16];
  __shared__ __align__(16) float sW1[2176];
  __shared__ float sB1[128];
  const int tid=threadIdx.x;
  const int b=tid>>4, hh=tid&15;
  for(int i=tid;i<2176;i+=1024) sW1[i]=P.mdw1[i];
  if (tid<128) sB1[tid]=P.mdb1[tid];
  if (tid<64){
    const float* gp=g_G+((size_t)(64+tid)*128+127)*8;
    float om[8]; softmax8(gp,om);
#pragma unroll
    for(int e=0;e<8;e++) om_s[tid*8+e]=om[e];
    x_s[tid*17+16]=P.Remote[(size_t)tid*128*132+127*132+131];
  }
  x_s[b*17+hh]=g_HF[b*16+hh];
  __syncthreads();
  {
    float h=0.f;
#pragma unroll
    for(int e=0;e<8;e++){
      float acc=sB1[e*16+hh];
#pragma unroll
      for(int i=0;i<17;i++) acc=fmaf(x_s[b*17+i], sW1[e*272+i*16+hh], acc);
      h=fmaf(om_s[b*8+e],acc,h);
    }
    a_s[b*16+hh]=h;
  }
  __syncthreads();
  if (tid<16){
    float s1=0.f,s2=0.f;
    for(int bb=0;bb<64;bb++){ float v=a_s[bb*16+tid]; s1+=v; s2=fmaf(v,v,s2); }
    float m=s1*(1.f/64.f), v=s2*(1.f/64.f)-m*m;
    ms[tid]=m; rs[tid]=rsqrtf(v+1e-5f);
  }
  __syncthreads();
  {
    float h=a_s[b*16+hh];
    a_s[b*16+hh]=eluf(P.mdg[hh]*(h-ms[hh])*rs[hh]+P.mdbt[hh]);
  }
  __syncthreads();
  // export C[b][e*16+k] = om[b][e]*a[b][k]  and om
  for (int q=tid;q<8192;q+=1024){
    int bb=q>>7, m=q&127, e=m>>4, k=m&15;
    g_C[q]=om_s[bb*8+e]*a_s[bb*16+k];
  }
  if (tid<512) g_OMd[tid]=om_s[tid];
}

// ---------------- K5b: decoder output GEMM out = C @ mdw2_v + om.b2 --------
__global__ __launch_bounds__(256) void k5b_dec(Params P)
{
  __shared__ float sC[2][128], sOM[2][8];
  const int tid=threadIdx.x;
  const int b0=blockIdx.x*2;
  sC[tid>>7][tid&127]=g_C[(size_t)b0*128+tid];
  if (tid<16) sOM[tid>>3][tid&7]=g_OMd[b0*8+tid];
  __syncthreads();
  const int lb=tid>>7, o=tid&127;
  float acc=0.f;
#pragma unroll 4
  for (int m=0;m<128;m++) acc=fmaf(sC[lb][m], P.mdw2[(size_t)m*128+o], acc);
#pragma unroll
  for (int e=0;e<8;e++) acc=fmaf(sOM[lb][e], P.mdb2[e*128+o], acc);
  P.out[(size_t)(b0+lb)*128+o]=acc;
}

extern "C" void kernel_launch(void* const* d_in, const int* in_sizes, int n_in,
                              void* d_out, int out_size)
{
  Params P;
  const float** f = (const float**)d_in;
  P.Local=f[0]; P.Remote=f[1];
  P.gWih0=f[2]; P.gWhh0=f[3]; P.gbih0=f[4]; P.gbhh0=f[5];
  P.gWih1=f[6]; P.gWhh1=f[7]; P.gbih1=f[8]; P.gbhh1=f[9];
  if (in_sizes[10] == 16384) {
    P.aew1=f[10]; P.aeb1=f[11]; P.aew2=f[12]; P.aeb2=f[13]; P.aeg=f[14]; P.aebt=f[15];
    P.mdw1=f[16]; P.mdb1=f[17]; P.mdw2=f[18]; P.mdb2=f[19]; P.mdg=f[20]; P.mdbt=f[21];
    P.mWih0=f[22]; P.mWhh0=f[23]; P.mbih0=f[24]; P.mbhh0=f[25];
    P.mWih1=f[26]; P.mWhh1=f[27]; P.mbih1=f[28]; P.mbhh1=f[29];
  } else {
    P.mWih0=f[10]; P.mWhh0=f[11]; P.mbih0=f[12]; P.mbhh0=f[13];
    P.mWih1=f[14]; P.mWhh1=f[15]; P.mbih1=f[16]; P.mbhh1=f[17];
    P.aew1=f[18]; P.aeb1=f[19]; P.aew2=f[20]; P.aeb2=f[21]; P.aeg=f[22]; P.aebt=f[23];
    P.mdw1=f[24]; P.mdb1=f[25]; P.mdw2=f[26]; P.mdb2=f[27]; P.mdg=f[28]; P.mdbt=f[29];
  }
  P.out=(float*)d_out;

  k1_gate_gemm<<<288,256>>>(P);
  k2_mix<<<128,256>>>(P);
  k3_z<<<64,256>>>(P);
  k4_mgru<<<64,64>>>(P);
  k5a_dec<<<1,1024>>>(P);
  k5b_dec<<<32,256>>>(P);
}